// round 16
// baseline (speedup 1.0000x reference)
#include <cuda_runtime.h>
#include <cstdint>
#include <cstddef>

#define NMAX 100000
#define EMAX 1700000
#define FD 128

typedef unsigned long long ull;
typedef unsigned int uint;

// Scratch — static __device__ globals, referenced only from device code.
__device__ __align__(16) float g_dinv[NMAX];
__device__ __align__(16) float g_h[(size_t)NMAX * FD];   // GEMM output
__device__ __align__(16) float g_a[(size_t)NMAX * FD];   // layer-1 activation
__device__ int   g_is64;
// CSR
__device__ int   g_cnt[NMAX];
__device__ int   g_fill[NMAX];
__device__ int   g_rowptr[NMAX + 1];
__device__ int   g_bsum[128];
__device__ int   g_boff[128];
__device__ __align__(16) int2 g_epack[EMAX];   // {col, float-bits(norm)}

// ---------------- packed fp32x2 FMA (sm_103a FFMA2) ----------------
__device__ __forceinline__ ull ffma2(ull a, ull b, ull c) {
    ull d;
    asm("fma.rn.f32x2 %0, %1, %2, %3;" : "=l"(d) : "l"(a), "l"(b), "l"(c));
    return d;
}
__device__ __forceinline__ ull dup_f32(float a) {
    ull d;
    asm("mov.b64 %0, {%1, %2};" : "=l"(d) : "f"(a), "f"(a));
    return d;
}
__device__ __forceinline__ float2 unpack_f32x2(ull v) {
    float2 r;
    asm("mov.b64 {%0, %1}, %2;" : "=f"(r.x), "=f"(r.y) : "l"(v));
    return r;
}

// B smem anti-conflict mapping: byte = c*4 + (c>>5)*16, row stride 576 B.
__device__ __forceinline__ int bcol_byte(int c) { return c * 4 + ((c >> 5) << 4); }

// ---------------- zero + dtype detection ----------------
__global__ void zero_detect_kernel(const int* __restrict__ ei32, int E, int n) {
    int i = blockIdx.x * blockDim.x + threadIdx.x;
    if (i < n) { g_dinv[i] = 1.0f; g_cnt[i] = 0; g_fill[i] = 0; }
    if (blockIdx.x == 0) {
        __shared__ int snz;
        if (threadIdx.x == 0) snz = 0;
        __syncthreads();
        int cnt = E < 4096 ? E : 4096, nz = 0;
        for (int j = threadIdx.x; j < cnt; j += blockDim.x) nz |= ei32[2 * j + 1];
        if (nz) atomicOr(&snz, 1);
        __syncthreads();
        if (threadIdx.x == 0) g_is64 = (snz == 0) ? 1 : 0;
    }
}

__device__ __forceinline__ int edge_row(const int* ei32, int E, int e) {
    return g_is64 ? ei32[2 * (size_t)e] : ei32[e];
}
__device__ __forceinline__ int edge_col(const int* ei32, int E, int e) {
    return g_is64 ? ei32[2 * (size_t)E + 2 * (size_t)e] : ei32[(size_t)E + e];
}

// ---------------- degree + CSR build ----------------
__global__ void deg_count_kernel(const int* __restrict__ ei32,
                                 const float* __restrict__ w, int E) {
    int e = blockIdx.x * blockDim.x + threadIdx.x;
    if (e < E) {
        int r = edge_row(ei32, E, e);
        atomicAdd(&g_dinv[r], w[e]);
        atomicAdd(&g_cnt[r], 1);
    }
}

// block-local exclusive scan of g_cnt + dinv finalize
__global__ void scan_block_kernel(int n) {
    __shared__ int sh[1024];
    int i = blockIdx.x * 1024 + threadIdx.x;
    if (i < n) {
        float d = g_dinv[i];
        g_dinv[i] = d > 0.0f ? rsqrtf(d) : 0.0f;
    }
    int v = (i < n) ? g_cnt[i] : 0;
    sh[threadIdx.x] = v;
    __syncthreads();
    for (int off = 1; off < 1024; off <<= 1) {
        int t = (threadIdx.x >= off) ? sh[threadIdx.x - off] : 0;
        __syncthreads();
        sh[threadIdx.x] += t;
        __syncthreads();
    }
    if (i < n) g_rowptr[i] = sh[threadIdx.x] - v;
    if (threadIdx.x == 1023) g_bsum[blockIdx.x] = sh[1023];
}

__global__ void scan_bsum_kernel(int nb) {
    if (threadIdx.x == 0) {
        int acc = 0;
        for (int b = 0; b < nb; b++) { int t = g_bsum[b]; g_boff[b] = acc; acc += t; }
    }
}

__global__ void scan_add_kernel(int n, int E) {
    int i = blockIdx.x * 1024 + threadIdx.x;
    if (i < n) g_rowptr[i] += g_boff[i >> 10];
    if (i == n) g_rowptr[n] = E;
}

__global__ void fill_kernel(const int* __restrict__ ei32,
                            const float* __restrict__ w, int E) {
    int e = blockIdx.x * blockDim.x + threadIdx.x;
    if (e < E) {
        int r = edge_row(ei32, E, e);
        int c = edge_col(ei32, E, e);
        float nm = g_dinv[r] * w[e] * g_dinv[c];
        int idx = g_rowptr[r] + atomicAdd(&g_fill[r], 1);
        g_epack[idx] = make_int2(c, __float_as_int(nm));
    }
}

// ---------------- SGEMM (FFMA2, 512 threads, 4Mx8N tile, 2 CTAs/SM) ------
// 32 warps/SM for latency hiding. As transposed [k][132]; WsB padded rows.

template <bool SRC_GA>
__global__ __launch_bounds__(512, 2) void sgemm_kernel(
    const float* __restrict__ Aext, const float* __restrict__ W, int n)
{
    __shared__ float As[32][132];
    __shared__ __align__(16) char WsB[32 * 576];

    const int bm  = blockIdx.x * 128;
    const int tid = threadIdx.x;
    const int tm  = (tid >> 4) << 2;     // 32 m-groups of 4
    const int tn  = (tid & 15) << 3;     // 16 n-groups of 8

    ull acc2[4][4];
#pragma unroll
    for (int i = 0; i < 4; i++)
#pragma unroll
        for (int j = 0; j < 4; j++) acc2[i][j] = 0ull;

    char* const wrow0 = WsB + bcol_byte(tn);
    char* const wrow1 = WsB + bcol_byte(tn + 4);

    for (int k0 = 0; k0 < 128; k0 += 32) {
        // stage A tile 128x32 (transposed into As): 1024 float4 / 512 thr
#pragma unroll
        for (int i = 0; i < 2; i++) {
            int t  = tid + i * 512;          // 0..1023
            int r  = t >> 3;                 // 0..127
            int c4 = (t & 7) << 2;           // 0..28
            int gr = bm + r;
            float4 v = make_float4(0.f, 0.f, 0.f, 0.f);
            if (gr < n) {
                const float* src = SRC_GA ? g_a : Aext;
                v = *reinterpret_cast<const float4*>(src + (size_t)gr * FD + k0 + c4);
                if (SRC_GA) {
                    v.x = fmaxf(v.x, 0.f); v.y = fmaxf(v.y, 0.f);
                    v.z = fmaxf(v.z, 0.f); v.w = fmaxf(v.w, 0.f);
                }
            }
            As[c4 + 0][r] = v.x; As[c4 + 1][r] = v.y;
            As[c4 + 2][r] = v.z; As[c4 + 3][r] = v.w;
        }
        // stage W tile 32x128 into padded layout: 1024 float4 / 512 thr
#pragma unroll
        for (int i = 0; i < 2; i++) {
            int t  = tid + i * 512;
            int r  = t >> 5;                 // 0..31
            int c4 = (t & 31) << 2;          // 0..124
            float4 v = *reinterpret_cast<const float4*>(W + (size_t)(k0 + r) * FD + c4);
            *reinterpret_cast<float4*>(WsB + r * 576 + bcol_byte(c4)) = v;
        }
        __syncthreads();

#pragma unroll
        for (int k = 0; k < 32; k++) {
            float a[4];
            *reinterpret_cast<float4*>(a) = *reinterpret_cast<float4*>(&As[k][tm]);
            ulonglong2 bq0 = *reinterpret_cast<ulonglong2*>(wrow0 + k * 576);
            ulonglong2 bq1 = *reinterpret_cast<ulonglong2*>(wrow1 + k * 576);
            ull b2[4] = {bq0.x, bq0.y, bq1.x, bq1.y};
            ull ad[4];
#pragma unroll
            for (int i = 0; i < 4; i++) ad[i] = dup_f32(a[i]);
#pragma unroll
            for (int i = 0; i < 4; i++)
#pragma unroll
                for (int j = 0; j < 4; j++)
                    acc2[i][j] = ffma2(ad[i], b2[j], acc2[i][j]);
        }
        __syncthreads();
    }

#pragma unroll
    for (int i = 0; i < 4; i++) {
        int gr = bm + tm + i;
        if (gr < n) {
            float2 p0 = unpack_f32x2(acc2[i][0]);
            float2 p1 = unpack_f32x2(acc2[i][1]);
            float2 p2 = unpack_f32x2(acc2[i][2]);
            float2 p3 = unpack_f32x2(acc2[i][3]);
            *reinterpret_cast<float4*>(g_h + (size_t)gr * FD + tn) =
                make_float4(p0.x, p0.y, p1.x, p1.y);
            *reinterpret_cast<float4*>(g_h + (size_t)gr * FD + tn + 4) =
                make_float4(p2.x, p2.y, p3.x, p3.y);
        }
    }
}

// ---------------- CSR aggregation: one warp per node ----------------
template <bool DST_GA>
__global__ void agg_csr_kernel(const float* __restrict__ bias,
                               float* __restrict__ outExt, int n)
{
    int r    = (blockIdx.x * blockDim.x + threadIdx.x) >> 5;
    int lane = threadIdx.x & 31;
    if (r >= n) return;
    int f4 = lane << 2;

    float di = g_dinv[r];
    float s  = di * di;
    float4 hv = *reinterpret_cast<const float4*>(g_h + (size_t)r * FD + f4);
    float4 bv = *reinterpret_cast<const float4*>(bias + f4);
    float4 acc = make_float4(fmaf(s, hv.x, bv.x), fmaf(s, hv.y, bv.y),
                             fmaf(s, hv.z, bv.z), fmaf(s, hv.w, bv.w));

    int e   = g_rowptr[r];
    int end = g_rowptr[r + 1];
    for (; e + 2 <= end; e += 2) {
        int2 p0 = g_epack[e];
        int2 p1 = g_epack[e + 1];
        float n0 = __int_as_float(p0.y);
        float n1 = __int_as_float(p1.y);
        float4 h0 = *reinterpret_cast<const float4*>(g_h + (size_t)p0.x * FD + f4);
        float4 h1 = *reinterpret_cast<const float4*>(g_h + (size_t)p1.x * FD + f4);
        acc.x = fmaf(n0, h0.x, acc.x); acc.y = fmaf(n0, h0.y, acc.y);
        acc.z = fmaf(n0, h0.z, acc.z); acc.w = fmaf(n0, h0.w, acc.w);
        acc.x = fmaf(n1, h1.x, acc.x); acc.y = fmaf(n1, h1.y, acc.y);
        acc.z = fmaf(n1, h1.z, acc.z); acc.w = fmaf(n1, h1.w, acc.w);
    }
    if (e < end) {
        int2 p0 = g_epack[e];
        float n0 = __int_as_float(p0.y);
        float4 h0 = *reinterpret_cast<const float4*>(g_h + (size_t)p0.x * FD + f4);
        acc.x = fmaf(n0, h0.x, acc.x); acc.y = fmaf(n0, h0.y, acc.y);
        acc.z = fmaf(n0, h0.z, acc.z); acc.w = fmaf(n0, h0.w, acc.w);
    }

    float* dst = DST_GA ? g_a : outExt;
    *reinterpret_cast<float4*>(dst + (size_t)r * FD + f4) = acc;
}

// ---------------- launch ----------------
extern "C" void kernel_launch(void* const* d_in, const int* in_sizes, int n_in,
                              void* d_out, int out_size)
{
    const float* x    = (const float*)d_in[0];
    const int*   ei32 = (const int*)d_in[1];
    const float* ew   = (const float*)d_in[2];
    const float* W1   = (const float*)d_in[3];
    const float* b1   = (const float*)d_in[4];
    const float* W2   = (const float*)d_in[5];
    const float* b2   = (const float*)d_in[6];
    float* out = (float*)d_out;

    const int n = in_sizes[0] / FD;
    const int E = in_sizes[2];

    const int gemm_blocks = (n + 127) / 128;
    const int agg_blocks  = (n * 32 + 255) / 256;
    const int scan_blocks = (n + 1023) / 1024;

    zero_detect_kernel<<<(n + 255) / 256, 256>>>(ei32, E, n);         // 0
    deg_count_kernel<<<(E + 255) / 256, 256>>>(ei32, ew, E);          // 1
    scan_block_kernel<<<scan_blocks, 1024>>>(n);                      // 2 (+dinv)
    sgemm_kernel<false><<<gemm_blocks, 512>>>(x, W1, n);              // 3 <- profiled
    scan_bsum_kernel<<<1, 32>>>(scan_blocks);                         // 4
    scan_add_kernel<<<(n + 1024) / 1024, 1024>>>(n, E);               // 5
    fill_kernel<<<(E + 255) / 256, 256>>>(ei32, ew, E);               // 6
    agg_csr_kernel<true><<<agg_blocks, 256>>>(b1, nullptr, n);        // 7
    sgemm_kernel<true><<<gemm_blocks, 512>>>(nullptr, W2, n);         // 8
    agg_csr_kernel<false><<<agg_blocks, 256>>>(b2, out, n);           // 9
}

// round 17
// speedup vs baseline: 1.0652x; 1.0652x over previous
#include <cuda_runtime.h>
#include <cstdint>
#include <cstddef>

#define NMAX 100000
#define EMAX 1700000
#define FD 128

typedef unsigned long long ull;
typedef unsigned int uint;

// Scratch — static __device__ globals, referenced only from device code.
__device__ __align__(16) float g_dinv[NMAX];
__device__ __align__(16) float g_h[(size_t)NMAX * FD];   // GEMM output
__device__ __align__(16) float g_a[(size_t)NMAX * FD];   // layer-1 activation
__device__ int   g_is64;
// CSR
__device__ int   g_cnt[NMAX];
__device__ int   g_fill[NMAX];
__device__ int   g_rowptr[NMAX + 1];
__device__ int   g_bsum[128];
__device__ int   g_boff[128];
__device__ __align__(16) int2 g_epack[EMAX];   // {col, float-bits(norm)}

// ---------------- packed fp32x2 FMA (sm_103a FFMA2) ----------------
__device__ __forceinline__ ull ffma2(ull a, ull b, ull c) {
    ull d;
    asm("fma.rn.f32x2 %0, %1, %2, %3;" : "=l"(d) : "l"(a), "l"(b), "l"(c));
    return d;
}
__device__ __forceinline__ ull dup_f32(float a) {
    ull d;
    asm("mov.b64 %0, {%1, %2};" : "=l"(d) : "f"(a), "f"(a));
    return d;
}
__device__ __forceinline__ float2 unpack_f32x2(ull v) {
    float2 r;
    asm("mov.b64 {%0, %1}, %2;" : "=f"(r.x), "=f"(r.y) : "l"(v));
    return r;
}

// B smem anti-conflict mapping: byte = c*4 + (c>>5)*16, row stride 576 B.
__device__ __forceinline__ int bcol_byte(int c) { return c * 4 + ((c >> 5) << 4); }

// ---------------- zero + dtype detection ----------------
__global__ void zero_detect_kernel(const int* __restrict__ ei32, int E, int n) {
    int i = blockIdx.x * blockDim.x + threadIdx.x;
    if (i < n) { g_dinv[i] = 1.0f; g_cnt[i] = 0; g_fill[i] = 0; }
    if (blockIdx.x == 0) {
        __shared__ int snz;
        if (threadIdx.x == 0) snz = 0;
        __syncthreads();
        int cnt = E < 4096 ? E : 4096, nz = 0;
        for (int j = threadIdx.x; j < cnt; j += blockDim.x) nz |= ei32[2 * j + 1];
        if (nz) atomicOr(&snz, 1);
        __syncthreads();
        if (threadIdx.x == 0) g_is64 = (snz == 0) ? 1 : 0;
    }
}

__device__ __forceinline__ int edge_row(const int* ei32, int E, int e) {
    return g_is64 ? ei32[2 * (size_t)e] : ei32[e];
}
__device__ __forceinline__ int edge_col(const int* ei32, int E, int e) {
    return g_is64 ? ei32[2 * (size_t)E + 2 * (size_t)e] : ei32[(size_t)E + e];
}

// ---------------- degree + CSR build ----------------
__global__ void deg_count_kernel(const int* __restrict__ ei32,
                                 const float* __restrict__ w, int E) {
    int e = blockIdx.x * blockDim.x + threadIdx.x;
    if (e < E) {
        int r = edge_row(ei32, E, e);
        atomicAdd(&g_dinv[r], w[e]);
        atomicAdd(&g_cnt[r], 1);
    }
}

// block-local exclusive scan of g_cnt + dinv finalize (fused)
__global__ void scan_block_kernel(int n) {
    __shared__ int sh[1024];
    int i = blockIdx.x * 1024 + threadIdx.x;
    if (i < n) {
        float d = g_dinv[i];
        g_dinv[i] = d > 0.0f ? rsqrtf(d) : 0.0f;
    }
    int v = (i < n) ? g_cnt[i] : 0;
    sh[threadIdx.x] = v;
    __syncthreads();
    for (int off = 1; off < 1024; off <<= 1) {
        int t = (threadIdx.x >= off) ? sh[threadIdx.x - off] : 0;
        __syncthreads();
        sh[threadIdx.x] += t;
        __syncthreads();
    }
    if (i < n) g_rowptr[i] = sh[threadIdx.x] - v;
    if (threadIdx.x == 1023) g_bsum[blockIdx.x] = sh[1023];
}

__global__ void scan_bsum_kernel(int nb) {
    if (threadIdx.x == 0) {
        int acc = 0;
        for (int b = 0; b < nb; b++) { int t = g_bsum[b]; g_boff[b] = acc; acc += t; }
    }
}

__global__ void scan_add_kernel(int n, int E) {
    int i = blockIdx.x * 1024 + threadIdx.x;
    if (i < n) g_rowptr[i] += g_boff[i >> 10];
    if (i == n) g_rowptr[n] = E;
}

__global__ void fill_kernel(const int* __restrict__ ei32,
                            const float* __restrict__ w, int E) {
    int e = blockIdx.x * blockDim.x + threadIdx.x;
    if (e < E) {
        int r = edge_row(ei32, E, e);
        int c = edge_col(ei32, E, e);
        float nm = g_dinv[r] * w[e] * g_dinv[c];
        int idx = g_rowptr[r] + atomicAdd(&g_fill[r], 1);
        g_epack[idx] = make_int2(c, __float_as_int(nm));
    }
}

// ---------------- SGEMM (FFMA2, 8x8 tile, BK=32, 2 CTAs/SM) --------------
// R11-measured optimum: 81.3 us. As transposed [k][132]; WsB 576-B rows.

template <bool SRC_GA>
__global__ __launch_bounds__(256, 2) void sgemm_kernel(
    const float* __restrict__ Aext, const float* __restrict__ W, int n)
{
    __shared__ float As[32][132];
    __shared__ __align__(16) char WsB[32 * 576];

    const int bm  = blockIdx.x * 128;
    const int tid = threadIdx.x;
    const int tm  = (tid >> 4) << 3;
    const int tn  = (tid & 15) << 3;

    ull acc2[8][4];
#pragma unroll
    for (int i = 0; i < 8; i++)
#pragma unroll
        for (int j = 0; j < 4; j++) acc2[i][j] = 0ull;

    char* const wrow0 = WsB + bcol_byte(tn);
    char* const wrow1 = WsB + bcol_byte(tn + 4);

    for (int k0 = 0; k0 < 128; k0 += 32) {
#pragma unroll
        for (int i = 0; i < 4; i++) {
            int t  = tid + i * 256;
            int r  = t >> 3;
            int c4 = (t & 7) << 2;
            int gr = bm + r;
            float4 v = make_float4(0.f, 0.f, 0.f, 0.f);
            if (gr < n) {
                const float* src = SRC_GA ? g_a : Aext;
                v = *reinterpret_cast<const float4*>(src + (size_t)gr * FD + k0 + c4);
                if (SRC_GA) {
                    v.x = fmaxf(v.x, 0.f); v.y = fmaxf(v.y, 0.f);
                    v.z = fmaxf(v.z, 0.f); v.w = fmaxf(v.w, 0.f);
                }
            }
            As[c4 + 0][r] = v.x; As[c4 + 1][r] = v.y;
            As[c4 + 2][r] = v.z; As[c4 + 3][r] = v.w;
        }
#pragma unroll
        for (int i = 0; i < 4; i++) {
            int t  = tid + i * 256;
            int r  = t >> 5;
            int c4 = (t & 31) << 2;
            float4 v = *reinterpret_cast<const float4*>(W + (size_t)(k0 + r) * FD + c4);
            *reinterpret_cast<float4*>(WsB + r * 576 + bcol_byte(c4)) = v;
        }
        __syncthreads();

#pragma unroll
        for (int k = 0; k < 32; k++) {
            float a[8];
            *reinterpret_cast<float4*>(a)     = *reinterpret_cast<float4*>(&As[k][tm]);
            *reinterpret_cast<float4*>(a + 4) = *reinterpret_cast<float4*>(&As[k][tm + 4]);
            ulonglong2 bq0 = *reinterpret_cast<ulonglong2*>(wrow0 + k * 576);
            ulonglong2 bq1 = *reinterpret_cast<ulonglong2*>(wrow1 + k * 576);
            ull b2[4] = {bq0.x, bq0.y, bq1.x, bq1.y};
            ull ad[8];
#pragma unroll
            for (int i = 0; i < 8; i++) ad[i] = dup_f32(a[i]);
#pragma unroll
            for (int i = 0; i < 8; i++)
#pragma unroll
                for (int j = 0; j < 4; j++)
                    acc2[i][j] = ffma2(ad[i], b2[j], acc2[i][j]);
        }
        __syncthreads();
    }

#pragma unroll
    for (int i = 0; i < 8; i++) {
        int gr = bm + tm + i;
        if (gr < n) {
            float2 p0 = unpack_f32x2(acc2[i][0]);
            float2 p1 = unpack_f32x2(acc2[i][1]);
            float2 p2 = unpack_f32x2(acc2[i][2]);
            float2 p3 = unpack_f32x2(acc2[i][3]);
            *reinterpret_cast<float4*>(g_h + (size_t)gr * FD + tn) =
                make_float4(p0.x, p0.y, p1.x, p1.y);
            *reinterpret_cast<float4*>(g_h + (size_t)gr * FD + tn + 4) =
                make_float4(p2.x, p2.y, p3.x, p3.y);
        }
    }
}

// ---------------- CSR aggregation: one warp per node ----------------
template <bool DST_GA>
__global__ void agg_csr_kernel(const float* __restrict__ bias,
                               float* __restrict__ outExt, int n)
{
    int r    = (blockIdx.x * blockDim.x + threadIdx.x) >> 5;
    int lane = threadIdx.x & 31;
    if (r >= n) return;
    int f4 = lane << 2;

    float di = g_dinv[r];
    float s  = di * di;
    float4 hv = *reinterpret_cast<const float4*>(g_h + (size_t)r * FD + f4);
    float4 bv = *reinterpret_cast<const float4*>(bias + f4);
    float4 acc = make_float4(fmaf(s, hv.x, bv.x), fmaf(s, hv.y, bv.y),
                             fmaf(s, hv.z, bv.z), fmaf(s, hv.w, bv.w));

    int e   = g_rowptr[r];
    int end = g_rowptr[r + 1];
    for (; e + 2 <= end; e += 2) {
        int2 p0 = g_epack[e];
        int2 p1 = g_epack[e + 1];
        float n0 = __int_as_float(p0.y);
        float n1 = __int_as_float(p1.y);
        float4 h0 = *reinterpret_cast<const float4*>(g_h + (size_t)p0.x * FD + f4);
        float4 h1 = *reinterpret_cast<const float4*>(g_h + (size_t)p1.x * FD + f4);
        acc.x = fmaf(n0, h0.x, acc.x); acc.y = fmaf(n0, h0.y, acc.y);
        acc.z = fmaf(n0, h0.z, acc.z); acc.w = fmaf(n0, h0.w, acc.w);
        acc.x = fmaf(n1, h1.x, acc.x); acc.y = fmaf(n1, h1.y, acc.y);
        acc.z = fmaf(n1, h1.z, acc.z); acc.w = fmaf(n1, h1.w, acc.w);
    }
    if (e < end) {
        int2 p0 = g_epack[e];
        float n0 = __int_as_float(p0.y);
        float4 h0 = *reinterpret_cast<const float4*>(g_h + (size_t)p0.x * FD + f4);
        acc.x = fmaf(n0, h0.x, acc.x); acc.y = fmaf(n0, h0.y, acc.y);
        acc.z = fmaf(n0, h0.z, acc.z); acc.w = fmaf(n0, h0.w, acc.w);
    }

    float* dst = DST_GA ? g_a : outExt;
    *reinterpret_cast<float4*>(dst + (size_t)r * FD + f4) = acc;
}

// ---------------- launch ----------------
extern "C" void kernel_launch(void* const* d_in, const int* in_sizes, int n_in,
                              void* d_out, int out_size)
{
    const float* x    = (const float*)d_in[0];
    const int*   ei32 = (const int*)d_in[1];
    const float* ew   = (const float*)d_in[2];
    const float* W1   = (const float*)d_in[3];
    const float* b1   = (const float*)d_in[4];
    const float* W2   = (const float*)d_in[5];
    const float* b2   = (const float*)d_in[6];
    float* out = (float*)d_out;

    const int n = in_sizes[0] / FD;
    const int E = in_sizes[2];

    const int gemm_blocks = (n + 127) / 128;
    const int agg_blocks  = (n * 32 + 255) / 256;
    const int scan_blocks = (n + 1023) / 1024;

    zero_detect_kernel<<<(n + 255) / 256, 256>>>(ei32, E, n);         // 0
    deg_count_kernel<<<(E + 255) / 256, 256>>>(ei32, ew, E);          // 1
    scan_block_kernel<<<scan_blocks, 1024>>>(n);                      // 2 (+dinv)
    sgemm_kernel<false><<<gemm_blocks, 256>>>(x, W1, n);              // 3 <- profiled
    scan_bsum_kernel<<<1, 32>>>(scan_blocks);                         // 4
    scan_add_kernel<<<(n + 1024) / 1024, 1024>>>(n, E);               // 5
    fill_kernel<<<(E + 255) / 256, 256>>>(ei32, ew, E);               // 6
    agg_csr_kernel<true><<<agg_blocks, 256>>>(b1, nullptr, n);        // 7
    sgemm_kernel<true><<<gemm_blocks, 256>>>(nullptr, W2, n);         // 8
    agg_csr_kernel<false><<<agg_blocks, 256>>>(b2, out, n);           // 9
}